// round 7
// baseline (speedup 1.0000x reference)
#include <cuda_runtime.h>
#include <cstdint>

#define B_SZ 512
#define IN_F 512
#define OUT_F 100
#define KD 5
#define OC 500              // OUT_F * KD
#define LOG2E 1.4426950408889634f
#define NT 32               // number of batch tiles
#define TS 16               // tile size (NT*TS = B_SZ)
#define NP 528              // NT*(NT+1)/2 unordered tile pairs

// Scratch for M = (x @ T) * log2(e), laid out [b][o*5+k], 512x500 floats = 1MB
__device__ float g_M[B_SZ * OC];

__device__ __forceinline__ float ex2(float x) {
    float r;
    asm("ex2.approx.f32 %0, %1;" : "=f"(r) : "f"(x));
    return r;
}

// ---------------------------------------------------------------------------
// Kernel 1: M[b][oc] = sum_i x[b][i] * T[i][oc], scaled by log2e.
// Block: 512 threads = 64 oc-pair-lanes x 8 K-slices (kh). Each thread owns
// 8 b-rows x 2 consecutive oc (float2 T loads) over a 64-long K-slice.
// kh-slices reduced with a 3-step smem tree (16KB buffer). Grid (64, 4).
// Also zeroes `out` (blockIdx.y == 0 slice).
// ---------------------------------------------------------------------------
__global__ void __launch_bounds__(512) gemm_kernel(const float* __restrict__ x,
                                                   const float* __restrict__ T,
                                                   float* __restrict__ out) {
    __shared__ __align__(16) float xs[IN_F * 8];          // [i][bb], 16KB
    __shared__ __align__(16) float red[4 * 8 * 128];      // 4 slices, 16KB

    const int t = threadIdx.x;
    const int lane = t & 63;               // oc-pair lane
    const int kh = t >> 6;                 // 0..7
    const int b0 = blockIdx.x * 8;
    const int oc0 = blockIdx.y * 128;
    const int oc = oc0 + lane * 2;
    const bool ocv = (oc < OC);

    if (blockIdx.y == 0) {
        for (int idx = blockIdx.x * 512 + t; idx < B_SZ * OUT_F; idx += 64 * 512)
            out[idx] = 0.0f;
    }

    // cooperative transpose load: x[b0+bb][i] -> xs[i*8+bb]
    for (int idx = t; idx < IN_F * 8; idx += 512) {
        int bb = idx >> 9;
        int i = idx & (IN_F - 1);
        xs[i * 8 + bb] = x[(b0 + bb) * IN_F + i];
    }
    __syncthreads();

    float accx[8] = {0.f, 0.f, 0.f, 0.f, 0.f, 0.f, 0.f, 0.f};
    float accy[8] = {0.f, 0.f, 0.f, 0.f, 0.f, 0.f, 0.f, 0.f};

    if (ocv) {
        const float* tp = T + (size_t)(kh * 64) * OC + oc;
        const float* xp = xs + kh * 64 * 8;
#pragma unroll 8
        for (int i = 0; i < 64; i++) {
            float2 tv = *reinterpret_cast<const float2*>(tp + i * OC);
            float4 xa = *reinterpret_cast<const float4*>(xp + i * 8);
            float4 xb = *reinterpret_cast<const float4*>(xp + i * 8 + 4);
            accx[0] += xa.x * tv.x; accy[0] += xa.x * tv.y;
            accx[1] += xa.y * tv.x; accy[1] += xa.y * tv.y;
            accx[2] += xa.z * tv.x; accy[2] += xa.z * tv.y;
            accx[3] += xa.w * tv.x; accy[3] += xa.w * tv.y;
            accx[4] += xb.x * tv.x; accy[4] += xb.x * tv.y;
            accx[5] += xb.y * tv.x; accy[5] += xb.y * tv.y;
            accx[6] += xb.z * tv.x; accy[6] += xb.z * tv.y;
            accx[7] += xb.w * tv.x; accy[7] += xb.w * tv.y;
        }
    }

    // 3-step tree reduction of the 8 kh-slices through 4-slice smem buffer.
    // Step 1: kh 4..7 -> slices 0..3; kh 0..3 accumulate.
    {
        if (kh >= 4) {
            float* rp = red + (kh - 4) * 1024 + lane * 2;
#pragma unroll
            for (int bb = 0; bb < 8; bb++) {
                rp[bb * 128 + 0] = accx[bb];
                rp[bb * 128 + 1] = accy[bb];
            }
        }
        __syncthreads();
        if (kh < 4) {
            const float* rp = red + kh * 1024 + lane * 2;
#pragma unroll
            for (int bb = 0; bb < 8; bb++) {
                accx[bb] += rp[bb * 128 + 0];
                accy[bb] += rp[bb * 128 + 1];
            }
        }
        __syncthreads();
    }
    // Step 2: kh 2..3 -> slices 0..1; kh 0..1 accumulate.
    {
        if (kh == 2 || kh == 3) {
            float* rp = red + (kh - 2) * 1024 + lane * 2;
#pragma unroll
            for (int bb = 0; bb < 8; bb++) {
                rp[bb * 128 + 0] = accx[bb];
                rp[bb * 128 + 1] = accy[bb];
            }
        }
        __syncthreads();
        if (kh < 2) {
            const float* rp = red + kh * 1024 + lane * 2;
#pragma unroll
            for (int bb = 0; bb < 8; bb++) {
                accx[bb] += rp[bb * 128 + 0];
                accy[bb] += rp[bb * 128 + 1];
            }
        }
        __syncthreads();
    }
    // Step 3: kh 1 -> slice 0; kh 0 accumulates and stores.
    {
        if (kh == 1) {
            float* rp = red + lane * 2;
#pragma unroll
            for (int bb = 0; bb < 8; bb++) {
                rp[bb * 128 + 0] = accx[bb];
                rp[bb * 128 + 1] = accy[bb];
            }
        }
        __syncthreads();
        if (kh == 0 && ocv) {
#pragma unroll
            for (int bb = 0; bb < 8; bb++) {
                float2 o2;
                o2.x = (accx[bb] + red[bb * 128 + lane * 2 + 0]) * LOG2E;
                o2.y = (accy[bb] + red[bb * 128 + lane * 2 + 1]) * LOG2E;
                *reinterpret_cast<float2*>(&g_M[(size_t)(b0 + bb) * OC + oc]) = o2;
            }
        }
    }
}

// ---------------------------------------------------------------------------
// Kernel 2 (symmetric, high-occupancy): one block per unordered tile pair
// (ta <= tb), 32 tiles of 16 rows -> 528 blocks. Block 800 threads, ALL
// active: o = t>>3 (0..99), jl = t&7. Each thread holds 2 j-rows
// (j = tb*16 + jl + 8r). launch_bounds(800,2) -> 50 warps/SM resident,
// ~35 regs/thread: latency (LDS 29cyc, MUFU 16cyc) fully covered.
// e(i,j) -> accJ[r] (out[j]); transpose sum over the 16 j's reduced across
// 8 jl-lanes via shfl.bfly (xor 1,2,4) -> atomicAdd out[i] (off-diag only).
// Diagonal blocks subtract the self-term exp(0)=1.
// ---------------------------------------------------------------------------
__global__ void __launch_bounds__(800, 2) md_kernel(float* __restrict__ out) {
    __shared__ __align__(16) float ms[TS * OC];  // 32KB

    // decode blockIdx.x -> (ta, tb), upper triangle row-major
    int rem = blockIdx.x;
    int ta = 0;
    while (rem >= NT - ta) { rem -= NT - ta; ta++; }
    const int tb = ta + rem;
    const bool diag = (ta == tb);

    const int t = threadIdx.x;
    const int o = t >> 3;        // 0..99
    const int jl = t & 7;        // 0..7

    // stage tile_a: 16 rows x 500 floats = 2000 float4
    {
        const float4* src = reinterpret_cast<const float4*>(g_M + (size_t)ta * TS * OC);
        float4* dst = reinterpret_cast<float4*>(ms);
        for (int i = t; i < 2000; i += 800) dst[i] = src[i];
    }

    // load j-side rows into registers
    float a[2][5];
    float accJ[2];
#pragma unroll
    for (int r = 0; r < 2; r++) {
        const int j = tb * TS + jl + 8 * r;       // < 512 always
        const float* m = g_M + (size_t)j * OC + o * KD;
        a[r][0] = m[0]; a[r][1] = m[1]; a[r][2] = m[2];
        a[r][3] = m[3]; a[r][4] = m[4];
        accJ[r] = 0.f;
    }
    __syncthreads();

#pragma unroll
    for (int ii = 0; ii < TS; ii++) {
        const float* m = ms + ii * OC + o * KD;  // conflict-free banks
        float d0 = m[0], d1 = m[1], d2 = m[2], d3 = m[3], d4 = m[4];
        float loc = 0.f;
#pragma unroll
        for (int r = 0; r < 2; r++) {
            float pa = -fabsf(d0 - a[r][0]) - fabsf(d1 - a[r][1]);
            float qa = -fabsf(d2 - a[r][2]) - fabsf(d3 - a[r][3]);
            float n = (pa + qa) - fabsf(d4 - a[r][4]);
            float e = ex2(n);
            accJ[r] += e;
            loc += e;
        }
        if (!diag) {
            // sum over all 16 j's of tile_b: reduce across the 8 jl-lanes
            loc += __shfl_xor_sync(0xffffffffu, loc, 1);
            loc += __shfl_xor_sync(0xffffffffu, loc, 2);
            loc += __shfl_xor_sync(0xffffffffu, loc, 4);
            if (jl == 0)
                atomicAdd(&out[(ta * TS + ii) * OUT_F + o], loc);
        }
    }

#pragma unroll
    for (int r = 0; r < 2; r++) {
        float v = accJ[r] - (diag ? 1.0f : 0.0f);
        atomicAdd(&out[(tb * TS + jl + 8 * r) * OUT_F + o], v);
    }
}

extern "C" void kernel_launch(void* const* d_in, const int* in_sizes, int n_in,
                              void* d_out, int out_size) {
    const float* x = (const float*)d_in[0];   // [512, 512]
    const float* T = (const float*)d_in[1];   // [512, 100, 5] -> [512, 500]
    float* out = (float*)d_out;               // [512, 100]

    gemm_kernel<<<dim3(64, 4), 512>>>(x, T, out);
    md_kernel<<<NP, 800>>>(out);
}